// round 2
// baseline (speedup 1.0000x reference)
#include <cuda_runtime.h>
#include <math.h>

#define N 8192
#define D 512

// Scratch: K / d2 matrix (256 MB), row sums of squares, scaling vectors, reduction scalars.
__device__ float g_K[(size_t)N * N];
__device__ float g_sq[N];
__device__ float g_u[N];
__device__ float g_v[N];
__device__ int g_maxd2_bits;
__device__ int g_maxP_bits;

// ---------------------------------------------------------------------------
// init: reset accumulators (must happen every launch — graph replays!) and v=1
// ---------------------------------------------------------------------------
__global__ void k_init() {
    int t = blockIdx.x * blockDim.x + threadIdx.x;
    if (t < N) g_v[t] = 1.0f;
    if (t == 0) { g_maxd2_bits = 0; g_maxP_bits = 0; }
}

// ---------------------------------------------------------------------------
// sq[i] = sum_k X[i,k]^2   (one block of 128 threads per row, D/4 = 128 float4)
// ---------------------------------------------------------------------------
__global__ void k_sq(const float* __restrict__ X) {
    int row = blockIdx.x;
    const float4* xr = (const float4*)(X + (size_t)row * D);
    float4 a = xr[threadIdx.x];
    float s = a.x * a.x + a.y * a.y + a.z * a.z + a.w * a.w;
    #pragma unroll
    for (int o = 16; o; o >>= 1) s += __shfl_down_sync(0xffffffffu, s, o);
    __shared__ float sh[4];
    if ((threadIdx.x & 31) == 0) sh[threadIdx.x >> 5] = s;
    __syncthreads();
    if (threadIdx.x == 0) g_sq[row] = sh[0] + sh[1] + sh[2] + sh[3];
}

// ---------------------------------------------------------------------------
// GEMM pass: d2[i,j] = sq[i] + sq[j] - 2 * X X^T, upper-triangle tiles only,
// mirror-written (exact symmetry). Also reduces global max(d2).
// 128x128 block tile, 8x8 per thread, BK=16, fp32.
// ---------------------------------------------------------------------------
__global__ void __launch_bounds__(256) k_gemm(const float* __restrict__ X) {
    const int nT = N / 128;  // 64
    int b = blockIdx.x, bi = 0;
    while (b >= nT - bi) { b -= nT - bi; bi++; }
    int bj = bi + b;

    __shared__ __align__(16) float As[16][132];
    __shared__ __align__(16) float Bs[16][132];

    int tid = threadIdx.x;
    int tx = tid & 15, ty = tid >> 4;

    float acc[8][8];
    #pragma unroll
    for (int i = 0; i < 8; i++)
        #pragma unroll
        for (int j = 0; j < 8; j++) acc[i][j] = 0.f;

    const float* Abase = X + (size_t)bi * 128 * D;
    const float* Bbase = X + (size_t)bj * 128 * D;
    int lr = tid >> 2;          // 0..63
    int lc = (tid & 3) << 2;    // 0,4,8,12

    for (int k0 = 0; k0 < D; k0 += 16) {
        #pragma unroll
        for (int h = 0; h < 2; h++) {
            int r = lr + 64 * h;
            float4 a = *(const float4*)(Abase + (size_t)r * D + k0 + lc);
            As[lc + 0][r] = a.x; As[lc + 1][r] = a.y;
            As[lc + 2][r] = a.z; As[lc + 3][r] = a.w;
            float4 q = *(const float4*)(Bbase + (size_t)r * D + k0 + lc);
            Bs[lc + 0][r] = q.x; Bs[lc + 1][r] = q.y;
            Bs[lc + 2][r] = q.z; Bs[lc + 3][r] = q.w;
        }
        __syncthreads();
        #pragma unroll
        for (int k = 0; k < 16; k++) {
            float4 a0 = *(const float4*)&As[k][ty * 8];
            float4 a1 = *(const float4*)&As[k][ty * 8 + 4];
            float4 b0 = *(const float4*)&Bs[k][tx * 8];
            float4 b1 = *(const float4*)&Bs[k][tx * 8 + 4];
            float af[8] = {a0.x, a0.y, a0.z, a0.w, a1.x, a1.y, a1.z, a1.w};
            float bf[8] = {b0.x, b0.y, b0.z, b0.w, b1.x, b1.y, b1.z, b1.w};
            #pragma unroll
            for (int i = 0; i < 8; i++)
                #pragma unroll
                for (int j = 0; j < 8; j++)
                    acc[i][j] = fmaf(af[i], bf[j], acc[i][j]);
        }
        __syncthreads();
    }

    int row0 = bi * 128 + ty * 8;
    int col0 = bj * 128 + tx * 8;
    float d2[8][8];
    float m = 0.f;
    #pragma unroll
    for (int i = 0; i < 8; i++) {
        float si = g_sq[row0 + i];
        #pragma unroll
        for (int j = 0; j < 8; j++) {
            float v = si + g_sq[col0 + j] - 2.f * acc[i][j];
            v = fmaxf(v, 0.f);
            d2[i][j] = v;
            m = fmaxf(m, v);
        }
    }
    #pragma unroll
    for (int i = 0; i < 8; i++) {
        float4* p = (float4*)(g_K + (size_t)(row0 + i) * N + col0);
        p[0] = make_float4(d2[i][0], d2[i][1], d2[i][2], d2[i][3]);
        p[1] = make_float4(d2[i][4], d2[i][5], d2[i][6], d2[i][7]);
    }
    if (bi != bj) {
        #pragma unroll
        for (int j = 0; j < 8; j++) {
            float4* p = (float4*)(g_K + (size_t)(col0 + j) * N + row0);
            p[0] = make_float4(d2[0][j], d2[1][j], d2[2][j], d2[3][j]);
            p[1] = make_float4(d2[4][j], d2[5][j], d2[6][j], d2[7][j]);
        }
    }
    __shared__ float red[256];
    red[tid] = m;
    __syncthreads();
    for (int s = 128; s; s >>= 1) {
        if (tid < s) red[tid] = fmaxf(red[tid], red[tid + s]);
        __syncthreads();
    }
    if (tid == 0) atomicMax(&g_maxd2_bits, __float_as_int(red[0]));
}

// ---------------------------------------------------------------------------
// exp pass (in place): K = exp(-10 * sqrt(d2)/maxM), diag -> 0
// ---------------------------------------------------------------------------
__global__ void k_exp() {
    const float inv_maxM = rsqrtf(__int_as_float(g_maxd2_bits));
    const int total4 = N * (N / 4);
    float4* K4 = (float4*)g_K;
    for (int idx = blockIdx.x * blockDim.x + threadIdx.x; idx < total4;
         idx += gridDim.x * blockDim.x) {
        int lin = idx << 2;
        int row = lin >> 13;
        int col = lin & (N - 1);
        float4 d = K4[idx];
        float4 r;
        r.x = (col + 0 == row) ? 0.f : __expf(-10.f * sqrtf(d.x) * inv_maxM);
        r.y = (col + 1 == row) ? 0.f : __expf(-10.f * sqrtf(d.y) * inv_maxM);
        r.z = (col + 2 == row) ? 0.f : __expf(-10.f * sqrtf(d.z) * inv_maxM);
        r.w = (col + 3 == row) ? 0.f : __expf(-10.f * sqrtf(d.w) * inv_maxM);
        K4[idx] = r;
    }
}

// ---------------------------------------------------------------------------
// Sinkhorn matvec: out[i] = 1 / sum_j K[i,j] * in[j]   (K symmetric)
// dir=0: u = 1/(K v);  dir=1: v = 1/(K u)
// One row per block, 256 threads, 8 float4 loads each (MLP ~8).
// ---------------------------------------------------------------------------
__global__ void __launch_bounds__(256) k_matvec(int dir) {
    const float* vin = dir ? g_u : g_v;
    float* vout = dir ? g_v : g_u;
    int row = blockIdx.x;
    const float4* Kr = (const float4*)(g_K + (size_t)row * N);
    const float4* v4 = (const float4*)vin;
    float s = 0.f;
    #pragma unroll
    for (int it = 0; it < (N / 4) / 256; it++) {
        int c = it * 256 + threadIdx.x;
        float4 k = __ldg(&Kr[c]);
        float4 w = __ldg(&v4[c]);
        s = fmaf(k.x, w.x, s);
        s = fmaf(k.y, w.y, s);
        s = fmaf(k.z, w.z, s);
        s = fmaf(k.w, w.w, s);
    }
    #pragma unroll
    for (int o = 16; o; o >>= 1) s += __shfl_down_sync(0xffffffffu, s, o);
    __shared__ float sh[8];
    if ((threadIdx.x & 31) == 0) sh[threadIdx.x >> 5] = s;
    __syncthreads();
    if (threadIdx.x < 8) {
        float t = sh[threadIdx.x];
        #pragma unroll
        for (int o = 4; o; o >>= 1) t += __shfl_down_sync(0xffu, t, o);
        if (threadIdx.x == 0) vout[row] = 1.0f / t;
    }
}

// ---------------------------------------------------------------------------
// maxP = max_ij u_i K_ij v_j   (diag K=0, so diagonal never wins)
// ---------------------------------------------------------------------------
__global__ void k_maxP() {
    const int total4 = N * (N / 4);
    const float4* K4 = (const float4*)g_K;
    float m = 0.f;
    for (int idx = blockIdx.x * blockDim.x + threadIdx.x; idx < total4;
         idx += gridDim.x * blockDim.x) {
        int lin = idx << 2;
        int row = lin >> 13;
        int col = lin & (N - 1);
        float u = __ldg(&g_u[row]);
        float4 k = K4[idx];
        float4 vv = *(const float4*)(g_v + col);
        m = fmaxf(m, u * k.x * vv.x);
        m = fmaxf(m, u * k.y * vv.y);
        m = fmaxf(m, u * k.z * vv.z);
        m = fmaxf(m, u * k.w * vv.w);
    }
    #pragma unroll
    for (int o = 16; o; o >>= 1) m = fmaxf(m, __shfl_down_sync(0xffffffffu, m, o));
    __shared__ float sh[8];
    if ((threadIdx.x & 31) == 0) sh[threadIdx.x >> 5] = m;
    __syncthreads();
    if (threadIdx.x < 8) {
        float t = sh[threadIdx.x];
        #pragma unroll
        for (int o = 4; o; o >>= 1) t = fmaxf(t, __shfl_down_sync(0xffu, t, o));
        if (threadIdx.x == 0) atomicMax(&g_maxP_bits, __float_as_int(t));
    }
}

// ---------------------------------------------------------------------------
// final: P = u_i K_ij v_j / maxP, diag -> 1
// ---------------------------------------------------------------------------
__global__ void k_final(float* __restrict__ out) {
    const float invP = 1.0f / __int_as_float(g_maxP_bits);
    const int total4 = N * (N / 4);
    const float4* K4 = (const float4*)g_K;
    float4* O4 = (float4*)out;
    for (int idx = blockIdx.x * blockDim.x + threadIdx.x; idx < total4;
         idx += gridDim.x * blockDim.x) {
        int lin = idx << 2;
        int row = lin >> 13;
        int col = lin & (N - 1);
        float u = __ldg(&g_u[row]);
        float4 k = K4[idx];
        float4 vv = *(const float4*)(g_v + col);
        float4 r;
        r.x = (col + 0 == row) ? 1.f : u * k.x * vv.x * invP;
        r.y = (col + 1 == row) ? 1.f : u * k.y * vv.y * invP;
        r.z = (col + 2 == row) ? 1.f : u * k.z * vv.z * invP;
        r.w = (col + 3 == row) ? 1.f : u * k.w * vv.w * invP;
        O4[idx] = r;
    }
}

// ---------------------------------------------------------------------------
extern "C" void kernel_launch(void* const* d_in, const int* in_sizes, int n_in,
                              void* d_out, int out_size) {
    const float* X = (const float*)d_in[0];
    float* out = (float*)d_out;

    k_init<<<(N + 255) / 256, 256>>>();
    k_sq<<<N, 128>>>(X);
    k_gemm<<<(64 * 65) / 2, 256>>>(X);
    k_exp<<<8192, 256>>>();
    for (int it = 0; it < 10; it++) {
        k_matvec<<<N, 256>>>(0);  // u = 1/(K v)
        k_matvec<<<N, 256>>>(1);  // v = 1/(K u)
    }
    k_maxP<<<8192, 256>>>();
    k_final<<<8192, 256>>>(out);
}

// round 5
// speedup vs baseline: 1.8144x; 1.8144x over previous
#include <cuda_runtime.h>
#include <cuda_bf16.h>
#include <math.h>
#include <cstdint>

#define N 8192
#define D 512

// Scratch
__device__ float g_K[(size_t)N * N];              // d2, then K (fp32)
__device__ __nv_bfloat16 g_Kb[(size_t)N * N];     // bf16 K for matvecs
__device__ __nv_bfloat16 g_Xh[(size_t)N * D];
__device__ __nv_bfloat16 g_Xl[(size_t)N * D];
__device__ float g_sq[N];
__device__ float g_u[N];
__device__ float g_v[N];
__device__ int g_maxd2_bits;
__device__ int g_maxP_bits;

// ---------------------------------------------------------------------------
__global__ void k_init() {
    int t = blockIdx.x * blockDim.x + threadIdx.x;
    if (t < N) g_v[t] = 1.0f;
    if (t == 0) { g_maxd2_bits = 0; g_maxP_bits = 0; }
}

// split X into bf16 hi/lo
__global__ void k_split(const float* __restrict__ X) {
    int i = blockIdx.x * blockDim.x + threadIdx.x;  // over N*D/4
    const float4* X4 = (const float4*)X;
    float4 x = X4[i];
    __nv_bfloat16 h0 = __float2bfloat16(x.x), h1 = __float2bfloat16(x.y);
    __nv_bfloat16 h2 = __float2bfloat16(x.z), h3 = __float2bfloat16(x.w);
    __nv_bfloat16 l0 = __float2bfloat16(x.x - __bfloat162float(h0));
    __nv_bfloat16 l1 = __float2bfloat16(x.y - __bfloat162float(h1));
    __nv_bfloat16 l2 = __float2bfloat16(x.z - __bfloat162float(h2));
    __nv_bfloat16 l3 = __float2bfloat16(x.w - __bfloat162float(h3));
    ((__nv_bfloat162*)g_Xh)[i * 2 + 0] = __nv_bfloat162(h0, h1);
    ((__nv_bfloat162*)g_Xh)[i * 2 + 1] = __nv_bfloat162(h2, h3);
    ((__nv_bfloat162*)g_Xl)[i * 2 + 0] = __nv_bfloat162(l0, l1);
    ((__nv_bfloat162*)g_Xl)[i * 2 + 1] = __nv_bfloat162(l2, l3);
}

__global__ void k_sq(const float* __restrict__ X) {
    int row = blockIdx.x;
    const float4* xr = (const float4*)(X + (size_t)row * D);
    float4 a = xr[threadIdx.x];
    float s = a.x * a.x + a.y * a.y + a.z * a.z + a.w * a.w;
    #pragma unroll
    for (int o = 16; o; o >>= 1) s += __shfl_down_sync(0xffffffffu, s, o);
    __shared__ float sh[4];
    if ((threadIdx.x & 31) == 0) sh[threadIdx.x >> 5] = s;
    __syncthreads();
    if (threadIdx.x == 0) g_sq[row] = sh[0] + sh[1] + sh[2] + sh[3];
}

// ---------------------------------------------------------------------------
// HMMA GEMM: 128x128 tile per CTA, upper-triangle tiles, mirrored via SMEM
// transpose. d2 = sq_i + sq_j - 2*(Hi*Hi^T + Hi*Lo^T + Lo*Hi^T), fp32 accum.
// ---------------------------------------------------------------------------
#define PITCH 144           // bytes per SMEM row (72 bf16): conflict-free frags
#define TILEB (128 * PITCH) // 18432 B per operand tile
#define SM_GEMM (4 * TILEB) // 73728 B dynamic

__device__ __forceinline__ void mma16816(float c[4], const uint32_t a[4], const uint32_t b[2]) {
    asm volatile(
        "mma.sync.aligned.m16n8k16.row.col.f32.bf16.bf16.f32 "
        "{%0,%1,%2,%3}, {%4,%5,%6,%7}, {%8,%9}, {%0,%1,%2,%3};"
        : "+f"(c[0]), "+f"(c[1]), "+f"(c[2]), "+f"(c[3])
        : "r"(a[0]), "r"(a[1]), "r"(a[2]), "r"(a[3]), "r"(b[0]), "r"(b[1]));
}
__device__ __forceinline__ void lda_frag(uint32_t f[4], const char* tile, int row, int kq) {
    const char* p = tile + row * PITCH + kq * 2;
    f[0] = *(const uint32_t*)(p);
    f[1] = *(const uint32_t*)(p + 8 * PITCH);
    f[2] = *(const uint32_t*)(p + 16);
    f[3] = *(const uint32_t*)(p + 8 * PITCH + 16);
}
__device__ __forceinline__ void ldb_frag(uint32_t f[2], const char* tile, int n, int kq) {
    const char* p = tile + n * PITCH + kq * 2;
    f[0] = *(const uint32_t*)(p);
    f[1] = *(const uint32_t*)(p + 16);
}

__global__ void __launch_bounds__(256, 2) k_gemm_mma() {
    extern __shared__ __align__(16) char smem[];
    char* sAh = smem;
    char* sAl = smem + TILEB;
    char* sBh = smem + 2 * TILEB;
    char* sBl = smem + 3 * TILEB;

    int tid = threadIdx.x, lane = tid & 31, wid = tid >> 5;
    int wm = wid & 3, wn = wid >> 2;  // 4 x 2 warp grid -> 32 x 64 per warp

    const int nT = N / 128;  // 64
    int b = blockIdx.x, bi = 0;
    while (b >= nT - bi) { b -= nT - bi; bi++; }
    int bj = bi + b;

    const __nv_bfloat16* gAh = g_Xh + (size_t)bi * 128 * D;
    const __nv_bfloat16* gAl = g_Xl + (size_t)bi * 128 * D;
    const __nv_bfloat16* gBh = g_Xh + (size_t)bj * 128 * D;
    const __nv_bfloat16* gBl = g_Xl + (size_t)bj * 128 * D;

    float acc[2][8][4];
    #pragma unroll
    for (int m = 0; m < 2; m++)
        #pragma unroll
        for (int n = 0; n < 8; n++)
            #pragma unroll
            for (int e = 0; e < 4; e++) acc[m][n][e] = 0.f;

    for (int chunk = 0; chunk < D / 64; chunk++) {
        int k0 = chunk * 64;
        #pragma unroll
        for (int t = 0; t < 4; t++) {
            int i = t * 256 + tid;        // 0..1023
            int row = i >> 3;
            int c8 = (i & 7) * 8;
            size_t go = (size_t)row * D + k0 + c8;
            uint32_t so = row * PITCH + c8 * 2;
            *(uint4*)(sAh + so) = *(const uint4*)(gAh + go);
            *(uint4*)(sAl + so) = *(const uint4*)(gAl + go);
            *(uint4*)(sBh + so) = *(const uint4*)(gBh + go);
            *(uint4*)(sBl + so) = *(const uint4*)(gBl + go);
        }
        __syncthreads();

        #pragma unroll
        for (int ks = 0; ks < 4; ks++) {
            int kq = ks * 16 + 2 * (lane & 3);
            int ra = wm * 32 + (lane >> 2);
            uint32_t ah0[4], ah1[4], al0[4], al1[4];
            lda_frag(ah0, sAh, ra, kq);
            lda_frag(ah1, sAh, ra + 16, kq);
            lda_frag(al0, sAl, ra, kq);
            lda_frag(al1, sAl, ra + 16, kq);
            #pragma unroll
            for (int nt = 0; nt < 8; nt++) {
                int nb = wn * 64 + nt * 8 + (lane >> 2);
                uint32_t bh[2], bl[2];
                ldb_frag(bh, sBh, nb, kq);
                ldb_frag(bl, sBl, nb, kq);
                mma16816(acc[0][nt], ah0, bh);
                mma16816(acc[1][nt], ah1, bh);
                mma16816(acc[0][nt], ah0, bl);
                mma16816(acc[1][nt], ah1, bl);
                mma16816(acc[0][nt], al0, bh);
                mma16816(acc[1][nt], al1, bh);
            }
        }
        __syncthreads();
    }

    int row0 = bi * 128, col0 = bj * 128;
    float mx = 0.f;
    #pragma unroll
    for (int mt = 0; mt < 2; mt++) {
        #pragma unroll
        for (int half = 0; half < 2; half++) {
            int r = row0 + wm * 32 + mt * 16 + half * 8 + (lane >> 2);
            float si = g_sq[r];
            #pragma unroll
            for (int nt = 0; nt < 8; nt++) {
                int c = col0 + wn * 64 + nt * 8 + (lane & 3) * 2;
                float g0 = acc[mt][nt][half * 2 + 0];
                float g1 = acc[mt][nt][half * 2 + 1];
                float v0 = fmaxf(si + __ldg(&g_sq[c + 0]) - 2.f * g0, 0.f);
                float v1 = fmaxf(si + __ldg(&g_sq[c + 1]) - 2.f * g1, 0.f);
                mx = fmaxf(mx, fmaxf(v0, v1));
                acc[mt][nt][half * 2 + 0] = v0;
                acc[mt][nt][half * 2 + 1] = v1;
                *(float2*)&g_K[(size_t)r * N + c] = make_float2(v0, v1);
            }
        }
    }

    if (bi != bj) {
        __syncthreads();
        float* smT = (float*)smem;  // pitch 132 floats: 128*132*4 = 67584 <= 73728
        #pragma unroll
        for (int mt = 0; mt < 2; mt++)
            #pragma unroll
            for (int half = 0; half < 2; half++) {
                int rl = wm * 32 + mt * 16 + half * 8 + (lane >> 2);
                #pragma unroll
                for (int nt = 0; nt < 8; nt++) {
                    int cl = wn * 64 + nt * 8 + (lane & 3) * 2;
                    smT[(cl + 0) * 132 + rl] = acc[mt][nt][half * 2 + 0];
                    smT[(cl + 1) * 132 + rl] = acc[mt][nt][half * 2 + 1];
                }
            }
        __syncthreads();
        #pragma unroll
        for (int t = 0; t < 16; t++) {
            int i = t * 256 + tid;
            int rr = i >> 5;
            int c4 = (i & 31) * 4;
            float4 v = *(float4*)&smT[rr * 132 + c4];
            *(float4*)&g_K[(size_t)(col0 + rr) * N + row0 + c4] = v;
        }
    }

    __shared__ float red[256];
    red[tid] = mx;
    __syncthreads();
    for (int s = 128; s; s >>= 1) {
        if (tid < s) red[tid] = fmaxf(red[tid], red[tid + s]);
        __syncthreads();
    }
    if (tid == 0) atomicMax(&g_maxd2_bits, __float_as_int(red[0]));
}

// ---------------------------------------------------------------------------
// exp pass: K = exp(-10*sqrt(d2)/maxM) fp32 in-place + bf16 copy, diag -> 0
// ---------------------------------------------------------------------------
__global__ void k_exp() {
    const float inv_maxM = rsqrtf(__int_as_float(g_maxd2_bits));
    const int total4 = N * (N / 4);
    float4* K4 = (float4*)g_K;
    __nv_bfloat162* Kb2 = (__nv_bfloat162*)g_Kb;
    for (int idx = blockIdx.x * blockDim.x + threadIdx.x; idx < total4;
         idx += gridDim.x * blockDim.x) {
        int lin = idx << 2;
        int row = lin >> 13;
        int col = lin & (N - 1);
        float4 d = K4[idx];
        float4 r;
        r.x = (col + 0 == row) ? 0.f : __expf(-10.f * sqrtf(d.x) * inv_maxM);
        r.y = (col + 1 == row) ? 0.f : __expf(-10.f * sqrtf(d.y) * inv_maxM);
        r.z = (col + 2 == row) ? 0.f : __expf(-10.f * sqrtf(d.z) * inv_maxM);
        r.w = (col + 3 == row) ? 0.f : __expf(-10.f * sqrtf(d.w) * inv_maxM);
        K4[idx] = r;
        Kb2[idx * 2 + 0] = __nv_bfloat162(__float2bfloat16(r.x), __float2bfloat16(r.y));
        Kb2[idx * 2 + 1] = __nv_bfloat162(__float2bfloat16(r.z), __float2bfloat16(r.w));
    }
}

// ---------------------------------------------------------------------------
// Sinkhorn matvec on bf16 K: out[i] = 1 / sum_j K[i,j]*in[j]
// ---------------------------------------------------------------------------
__global__ void __launch_bounds__(256) k_matvec(int dir) {
    const float* vin = dir ? g_u : g_v;
    float* vout = dir ? g_v : g_u;
    int row = blockIdx.x;
    const uint4* Kr = (const uint4*)(g_Kb + (size_t)row * N);  // 8 bf16 per uint4
    float s = 0.f;
    #pragma unroll
    for (int it = 0; it < (N / 8) / 256; it++) {  // 4 iters
        int c = it * 256 + threadIdx.x;
        uint4 k = __ldg(&Kr[c]);
        const float4* vv = (const float4*)(vin + c * 8);
        float4 v0 = __ldg(&vv[0]);
        float4 v1 = __ldg(&vv[1]);
        float2 p0 = __bfloat1622float2(*(const __nv_bfloat162*)&k.x);
        float2 p1 = __bfloat1622float2(*(const __nv_bfloat162*)&k.y);
        float2 p2 = __bfloat1622float2(*(const __nv_bfloat162*)&k.z);
        float2 p3 = __bfloat1622float2(*(const __nv_bfloat162*)&k.w);
        s = fmaf(p0.x, v0.x, s); s = fmaf(p0.y, v0.y, s);
        s = fmaf(p1.x, v0.z, s); s = fmaf(p1.y, v0.w, s);
        s = fmaf(p2.x, v1.x, s); s = fmaf(p2.y, v1.y, s);
        s = fmaf(p3.x, v1.z, s); s = fmaf(p3.y, v1.w, s);
    }
    #pragma unroll
    for (int o = 16; o; o >>= 1) s += __shfl_down_sync(0xffffffffu, s, o);
    __shared__ float sh[8];
    if ((threadIdx.x & 31) == 0) sh[threadIdx.x >> 5] = s;
    __syncthreads();
    if (threadIdx.x < 8) {
        float t = sh[threadIdx.x];
        #pragma unroll
        for (int o = 4; o; o >>= 1) t += __shfl_down_sync(0xffu, t, o);
        if (threadIdx.x == 0) vout[row] = 1.0f / t;
    }
}

// ---------------------------------------------------------------------------
__global__ void k_maxP() {
    const int total4 = N * (N / 4);
    const float4* K4 = (const float4*)g_K;
    float m = 0.f;
    for (int idx = blockIdx.x * blockDim.x + threadIdx.x; idx < total4;
         idx += gridDim.x * blockDim.x) {
        int lin = idx << 2;
        int row = lin >> 13;
        int col = lin & (N - 1);
        float u = __ldg(&g_u[row]);
        float4 k = K4[idx];
        float4 vv = *(const float4*)(g_v + col);
        m = fmaxf(m, u * k.x * vv.x);
        m = fmaxf(m, u * k.y * vv.y);
        m = fmaxf(m, u * k.z * vv.z);
        m = fmaxf(m, u * k.w * vv.w);
    }
    #pragma unroll
    for (int o = 16; o; o >>= 1) m = fmaxf(m, __shfl_down_sync(0xffffffffu, m, o));
    __shared__ float sh[8];
    if ((threadIdx.x & 31) == 0) sh[threadIdx.x >> 5] = m;
    __syncthreads();
    if (threadIdx.x < 8) {
        float t = sh[threadIdx.x];
        #pragma unroll
        for (int o = 4; o; o >>= 1) t = fmaxf(t, __shfl_down_sync(0xffu, t, o));
        if (threadIdx.x == 0) atomicMax(&g_maxP_bits, __float_as_int(t));
    }
}

__global__ void k_final(float* __restrict__ out) {
    const float invP = 1.0f / __int_as_float(g_maxP_bits);
    const int total4 = N * (N / 4);
    const float4* K4 = (const float4*)g_K;
    float4* O4 = (float4*)out;
    for (int idx = blockIdx.x * blockDim.x + threadIdx.x; idx < total4;
         idx += gridDim.x * blockDim.x) {
        int lin = idx << 2;
        int row = lin >> 13;
        int col = lin & (N - 1);
        float u = __ldg(&g_u[row]);
        float4 k = K4[idx];
        float4 vv = *(const float4*)(g_v + col);
        float4 r;
        r.x = (col + 0 == row) ? 1.f : u * k.x * vv.x * invP;
        r.y = (col + 1 == row) ? 1.f : u * k.y * vv.y * invP;
        r.z = (col + 2 == row) ? 1.f : u * k.z * vv.z * invP;
        r.w = (col + 3 == row) ? 1.f : u * k.w * vv.w * invP;
        O4[idx] = r;
    }
}

// ---------------------------------------------------------------------------
extern "C" void kernel_launch(void* const* d_in, const int* in_sizes, int n_in,
                              void* d_out, int out_size) {
    const float* X = (const float*)d_in[0];
    float* out = (float*)d_out;

    cudaFuncSetAttribute(k_gemm_mma, cudaFuncAttributeMaxDynamicSharedMemorySize, SM_GEMM);

    k_init<<<(N + 255) / 256, 256>>>();
    k_split<<<(N * D / 4) / 256, 256>>>(X);
    k_sq<<<N, 128>>>(X);
    k_gemm_mma<<<(64 * 65) / 2, 256, SM_GEMM>>>();
    k_exp<<<8192, 256>>>();
    for (int it = 0; it < 10; it++) {
        k_matvec<<<N, 256>>>(0);
        k_matvec<<<N, 256>>>(1);
    }
    k_maxP<<<8192, 256>>>();
    k_final<<<8192, 256>>>(out);
}